// round 15
// baseline (speedup 1.0000x reference)
#include <cuda_runtime.h>
#include <cstdint>

#define NF  256
#define GS  16
#define NG  16
#define HWS 3136        // 56*56
#define MB  32
#define NTOT (MB*HWS)   // 100352
#define NPAIR 136       // 16*17/2
#define NF2  (HWS/2)    // 1568 float2 positions
#define NF4  (HWS/4)    // 784  float4 positions
#define SS   4          // spatial split for stats
#define CH2  (NF2/SS)   // 392 float2 positions per stats chunk
#define NBLK (MB*SS)    // 128 stats blocks per group

typedef unsigned long long u64;

// Scratch (device globals). All start zeroed at module load. Replay
// invariants: the solver block re-zeroes g_sig[g] and g_cnt[g].
__device__ float g_sig[NG][152];
__device__ int   g_cnt[NG];
__device__ float g_W[NG][NPAIR];
__device__ float g_b[NG][GS];

// ---------------------------------------------------------------------------
// packed f32x2 helpers
// ---------------------------------------------------------------------------
__device__ __forceinline__ u64 ffma2(u64 a, u64 b, u64 c) {
    u64 d;
    asm("fma.rn.f32x2 %0, %1, %2, %3;" : "=l"(d) : "l"(a), "l"(b), "l"(c));
    return d;
}
__device__ __forceinline__ float2 u2f2(u64 v) {
    float2 f;
    asm("mov.b64 {%0, %1}, %2;" : "=f"(f.x), "=f"(f.y) : "l"(v));
    return f;
}

// ---------------------------------------------------------------------------
// One-warp solve for group g. Runs in a dedicated solver block inside the
// stats kernel's ragged tail (overlapped with other groups' stats work).
// ---------------------------------------------------------------------------
__device__ void solve_group(int g, int lane) {
    __shared__ float a [GS][GS + 1];
    __shared__ float w [GS][GS + 1];
    __shared__ float mu[GS];
    __shared__ float red[152];

    const float n = (float)NTOT;

    for (int e = lane; e < 152; e += 32) red[e] = __ldcg(&g_sig[g][e]);
    __syncwarp();

    if (lane < GS) mu[lane] = red[136 + lane] / n;
    __syncwarp();

    for (int idx = lane; idx < 256; idx += 32) {
        const int i = idx >> 4, j = idx & 15;
        const int ii = i > j ? i : j;
        const int jj = i > j ? j : i;
        float G = red[ii * (ii + 1) / 2 + jj];
        float sh = (G - n * mu[i] * mu[j]) / (n - 1.0f);
        a[i][j] = (1.0f - 1e-6f) * sh + ((i == j) ? 1e-6f : 0.0f);
    }
    __syncwarp();

    for (int j = 0; j < GS; j++) {
        if (lane == j) a[j][j] = sqrtf(a[j][j]);
        __syncwarp();
        const float tjj = a[j][j];
        if (lane > j && lane < GS) a[lane][j] /= tjj;
        __syncwarp();
        if (lane > j && lane < GS) {
            const float lij = a[lane][j];
            for (int k = j + 1; k <= lane; k++)
                a[lane][k] -= lij * a[k][j];
        }
        __syncwarp();
    }

    if (lane < GS) {
        const int j = lane;
        w[j][j] = 1.0f / a[j][j];
        for (int i = j + 1; i < GS; i++) {
            float s = 0.f;
            for (int k = j; k < i; k++) s += a[i][k] * w[k][j];
            w[i][j] = -s / a[i][i];
        }
        for (int i = j; i < GS; i++)
            g_W[g][i * (i + 1) / 2 + j] = w[i][j];
    }
    __syncwarp();

    if (lane < GS) {
        const int i = lane;
        float b = 0.f;
        for (int j = 0; j <= i; j++) b += w[i][j] * mu[j];
        g_b[g][i] = b;
    }

    // replay invariants
    for (int e = lane; e < 152; e += 32) g_sig[g][e] = 0.f;
    if (lane == 0) g_cnt[g] = 0;
}

// ---------------------------------------------------------------------------
// Stats hot path: EXACT R6 quarter-block warps (measured 39-44us, 64 regs).
// ---------------------------------------------------------------------------
template<int QI, int QJ>
__device__ __forceinline__ void qb_warp(const float* __restrict__ base,
                                        int lane, int f0, int g) {
    constexpr bool DIAG = (QI == QJ);
    constexpr int NACC = DIAG ? 10 : 16;

    u64 acc[NACC];
#pragma unroll
    for (int k = 0; k < NACC; k++) acc[k] = 0ull;
    float s[4];
#pragma unroll
    for (int c = 0; c < 4; c++) s[c] = 0.f;

    const int f1 = f0 + CH2;
    for (int f = f0 + lane; f < f1; f += 32) {   // ~12.25 iterations
        u64 va[4];
#pragma unroll
        for (int a = 0; a < 4; a++)
            va[a] = ((const u64*)(base + (size_t)(4 * QI + a) * HWS))[f];
        if (DIAG) {
            int k = 0;
#pragma unroll
            for (int a = 0; a < 4; a++) {
#pragma unroll
                for (int b = 0; b <= a; b++) { acc[k] = ffma2(va[a], va[b], acc[k]); k++; }
                float2 t = u2f2(va[a]);
                s[a] += t.x + t.y;
            }
        } else {
            u64 vb[4];
#pragma unroll
            for (int b = 0; b < 4; b++)
                vb[b] = ((const u64*)(base + (size_t)(4 * QJ + b) * HWS))[f];
#pragma unroll
            for (int a = 0; a < 4; a++)
#pragma unroll
                for (int b = 0; b < 4; b++)
                    acc[a * 4 + b] = ffma2(va[a], vb[b], acc[a * 4 + b]);
        }
    }

    static const int DA[10] = {0,1,1,2,2,2,3,3,3,3};
    static const int DB[10] = {0,0,1,0,1,2,0,1,2,3};
#pragma unroll
    for (int t = 0; t < NACC; t++) {
        float2 p = u2f2(acc[t]);
        float v = p.x + p.y;
#pragma unroll
        for (int sh = 16; sh > 0; sh >>= 1)
            v += __shfl_xor_sync(0xFFFFFFFFu, v, sh);
        if (lane == 0) {
            const int a = DIAG ? DA[t] : (t >> 2);
            const int b = DIAG ? DB[t] : (t & 3);
            const int i = 4 * QI + a;
            const int j = 4 * QJ + b;
            atomicAdd(&g_sig[g][i * (i + 1) / 2 + j], v);
        }
    }
    if (DIAG) {
#pragma unroll
        for (int c = 0; c < 4; c++) {
            float v = s[c];
#pragma unroll
            for (int sh = 16; sh > 0; sh >>= 1)
                v += __shfl_xor_sync(0xFFFFFFFFu, v, sh);
            if (lane == 0) atomicAdd(&g_sig[g][136 + 4 * QI + c], v);
        }
    }
}

// ---------------------------------------------------------------------------
// Stats kernel, grid (16, 32, SS+1):
//   z <  SS          : stats work for (g, m, z), then bump g_cnt[g].
//   z == SS && m == 0: solver block for group g — spin until g_cnt[g]==NBLK,
//                      then solve in the ragged tail. (16 blocks)
//   z == SS && m > 0 : exit immediately.
// ---------------------------------------------------------------------------
__global__ __launch_bounds__(320, 3) void stats_kernel(const float* __restrict__ x) {
    const int g = blockIdx.x;
    const int m = blockIdx.y;
    const int z = blockIdx.z;
    const int tid  = threadIdx.x;
    const int wid  = tid >> 5;
    const int lane = tid & 31;

    if (z == SS) {
        if (m == 0 && wid == 0) {
            if (lane == 0)
                while (atomicAdd(&g_cnt[g], 0) < NBLK) __nanosleep(100);
            __syncwarp();
            __threadfence();   // acquire g_sig atomics
            solve_group(g, lane);
        }
        return;
    }

    const float* base = x + ((size_t)m * NF + (size_t)g * GS) * HWS;
    const int f0 = z * CH2;
    switch (wid) {
        case 0: qb_warp<0,0>(base, lane, f0, g); break;
        case 1: qb_warp<1,0>(base, lane, f0, g); break;
        case 2: qb_warp<1,1>(base, lane, f0, g); break;
        case 3: qb_warp<2,0>(base, lane, f0, g); break;
        case 4: qb_warp<2,1>(base, lane, f0, g); break;
        case 5: qb_warp<2,2>(base, lane, f0, g); break;
        case 6: qb_warp<3,0>(base, lane, f0, g); break;
        case 7: qb_warp<3,1>(base, lane, f0, g); break;
        case 8: qb_warp<3,2>(base, lane, f0, g); break;
        case 9: qb_warp<3,3>(base, lane, f0, g); break;
    }

    __threadfence();     // make this block's g_sig atomics globally visible
    __syncthreads();
    if (tid == 0) atomicAdd(&g_cnt[g], 1);
}

// ---------------------------------------------------------------------------
// Whiten: PURE R2 measured-best body (38.8us): grid (16,32), 128 threads,
// buffered v[16]/y[16] float4, plain stores. No prologue, no spin.
// ---------------------------------------------------------------------------
__global__ __launch_bounds__(128) void whiten_kernel(const float* __restrict__ x,
                                                     float* __restrict__ out) {
    const int g = blockIdx.x;
    const int m = blockIdx.y;

    __shared__ float sW[NPAIR];
    __shared__ float sb[GS];
    for (int i = threadIdx.x; i < NPAIR + GS; i += 128) {
        if (i < NPAIR) sW[i] = g_W[g][i];
        else           sb[i - NPAIR] = g_b[g][i - NPAIR];
    }
    __syncthreads();

    const size_t base = ((size_t)m * NF + (size_t)g * GS) * HWS;

    for (int f = threadIdx.x; f < NF4; f += 128) {
        float4 v[GS];
#pragma unroll
        for (int c = 0; c < GS; c++)
            v[c] = ((const float4*)(x + base + (size_t)c * HWS))[f];

        float4 y[GS];
#pragma unroll
        for (int i = 0; i < GS; i++) {
            const float b = sb[i];
            y[i].x = -b; y[i].y = -b; y[i].z = -b; y[i].w = -b;
#pragma unroll
            for (int j = 0; j <= i; j++) {
                const float w = sW[i * (i + 1) / 2 + j];
                y[i].x = fmaf(w, v[j].x, y[i].x);
                y[i].y = fmaf(w, v[j].y, y[i].y);
                y[i].z = fmaf(w, v[j].z, y[i].z);
                y[i].w = fmaf(w, v[j].w, y[i].w);
            }
        }

#pragma unroll
        for (int c = 0; c < GS; c++)
            ((float4*)(out + base + (size_t)c * HWS))[f] = y[c];
    }
}

// ---------------------------------------------------------------------------
extern "C" void kernel_launch(void* const* d_in, const int* in_sizes, int n_in,
                              void* d_out, int out_size) {
    const float* x = (const float*)d_in[0];
    float* out = (float*)d_out;

    dim3 sgrid(NG, MB, SS + 1);
    stats_kernel<<<sgrid, 320>>>(x);
    dim3 wgrid(NG, MB);
    whiten_kernel<<<wgrid, 128>>>(x, out);
}

// round 16
// speedup vs baseline: 1.0642x; 1.0642x over previous
#include <cuda_runtime.h>
#include <cstdint>

#define NF  256
#define GS  16
#define NG  16
#define HWS 3136        // 56*56
#define MB  32
#define NTOT (MB*HWS)   // 100352
#define NPAIR 136       // 16*17/2
#define NF2  (HWS/2)    // 1568 float2 positions
#define NF4  (HWS/4)    // 784  float4 positions
#define SS   4          // spatial split for stats
#define CH2  (NF2/SS)   // 392 float2 positions per stats chunk

typedef unsigned long long u64;

// Scratch (device globals). g_sig/g_done start zeroed. Replay invariants:
// stats resets g_done[g]; the whiten-prologue solve re-zeroes g_sig[g].
__device__ float g_sig[NG][152];
__device__ int   g_done[NG];
__device__ float g_W[NG][NPAIR];
__device__ float g_b[NG][GS];

// ---------------------------------------------------------------------------
// packed f32x2 helpers
// ---------------------------------------------------------------------------
__device__ __forceinline__ u64 ffma2(u64 a, u64 b, u64 c) {
    u64 d;
    asm("fma.rn.f32x2 %0, %1, %2, %3;" : "=l"(d) : "l"(a), "l"(b), "l"(c));
    return d;
}
__device__ __forceinline__ float2 u2f2(u64 v) {
    float2 f;
    asm("mov.b64 {%0, %1}, %2;" : "=f"(f.x), "=f"(f.y) : "l"(v));
    return f;
}

// ---------------------------------------------------------------------------
// Kernel 1: EXACT R6 stats hot path (measured 39-44us, 64 regs, 3 blk/SM).
// (m==0,z==0) block also resets g_done[g] for this replay.
// ---------------------------------------------------------------------------
template<int QI, int QJ>
__device__ __forceinline__ void qb_warp(const float* __restrict__ base,
                                        int lane, int f0, int g) {
    constexpr bool DIAG = (QI == QJ);
    constexpr int NACC = DIAG ? 10 : 16;

    u64 acc[NACC];
#pragma unroll
    for (int k = 0; k < NACC; k++) acc[k] = 0ull;
    float s[4];
#pragma unroll
    for (int c = 0; c < 4; c++) s[c] = 0.f;

    const int f1 = f0 + CH2;
    for (int f = f0 + lane; f < f1; f += 32) {
        u64 va[4];
#pragma unroll
        for (int a = 0; a < 4; a++)
            va[a] = ((const u64*)(base + (size_t)(4 * QI + a) * HWS))[f];
        if (DIAG) {
            int k = 0;
#pragma unroll
            for (int a = 0; a < 4; a++) {
#pragma unroll
                for (int b = 0; b <= a; b++) { acc[k] = ffma2(va[a], va[b], acc[k]); k++; }
                float2 t = u2f2(va[a]);
                s[a] += t.x + t.y;
            }
        } else {
            u64 vb[4];
#pragma unroll
            for (int b = 0; b < 4; b++)
                vb[b] = ((const u64*)(base + (size_t)(4 * QJ + b) * HWS))[f];
#pragma unroll
            for (int a = 0; a < 4; a++)
#pragma unroll
                for (int b = 0; b < 4; b++)
                    acc[a * 4 + b] = ffma2(va[a], vb[b], acc[a * 4 + b]);
        }
    }

    static const int DA[10] = {0,1,1,2,2,2,3,3,3,3};
    static const int DB[10] = {0,0,1,0,1,2,0,1,2,3};
#pragma unroll
    for (int t = 0; t < NACC; t++) {
        float2 p = u2f2(acc[t]);
        float v = p.x + p.y;
#pragma unroll
        for (int sh = 16; sh > 0; sh >>= 1)
            v += __shfl_xor_sync(0xFFFFFFFFu, v, sh);
        if (lane == 0) {
            const int a = DIAG ? DA[t] : (t >> 2);
            const int b = DIAG ? DB[t] : (t & 3);
            const int i = 4 * QI + a;
            const int j = 4 * QJ + b;
            atomicAdd(&g_sig[g][i * (i + 1) / 2 + j], v);
        }
    }
    if (DIAG) {
#pragma unroll
        for (int c = 0; c < 4; c++) {
            float v = s[c];
#pragma unroll
            for (int sh = 16; sh > 0; sh >>= 1)
                v += __shfl_xor_sync(0xFFFFFFFFu, v, sh);
            if (lane == 0) atomicAdd(&g_sig[g][136 + 4 * QI + c], v);
        }
    }
}

__global__ __launch_bounds__(320, 3) void stats_kernel(const float* __restrict__ x) {
    const int g = blockIdx.x;
    const int m = blockIdx.y;
    const int z = blockIdx.z;

    if (m == 0 && z == 0 && threadIdx.x == 0) g_done[g] = 0;

    const float* base = x + ((size_t)m * NF + (size_t)g * GS) * HWS;
    const int wid  = threadIdx.x >> 5;
    const int lane = threadIdx.x & 31;
    const int f0 = z * CH2;
    switch (wid) {
        case 0: qb_warp<0,0>(base, lane, f0, g); break;
        case 1: qb_warp<1,0>(base, lane, f0, g); break;
        case 2: qb_warp<1,1>(base, lane, f0, g); break;
        case 3: qb_warp<2,0>(base, lane, f0, g); break;
        case 4: qb_warp<2,1>(base, lane, f0, g); break;
        case 5: qb_warp<2,2>(base, lane, f0, g); break;
        case 6: qb_warp<3,0>(base, lane, f0, g); break;
        case 7: qb_warp<3,1>(base, lane, f0, g); break;
        case 8: qb_warp<3,2>(base, lane, f0, g); break;
        case 9: qb_warp<3,3>(base, lane, f0, g); break;
    }
}

// ---------------------------------------------------------------------------
// Kernel 2: whiten with fast in-prologue solve (R14 structure, best at
// 100.9us). Blocks (g, m=0) solve group g with a low-latency solver:
//   - rsqrtf instead of sqrt+divide in Cholesky
//   - precomputed fast reciprocals: all inverse divides become multiplies
//   - sigma build parallel over 128 threads
// then release g_done[g]; other blocks spin briefly and run the measured-
// best whiten body.
// ---------------------------------------------------------------------------
__global__ __launch_bounds__(128) void whiten_kernel(const float* __restrict__ x,
                                                     float* __restrict__ out) {
    const int g = blockIdx.x;
    const int m = blockIdx.y;
    const int tid = threadIdx.x;

    __shared__ float sW[NPAIR];
    __shared__ float sb[GS];

    if (m == 0) {
        __shared__ float a  [GS][GS + 1];
        __shared__ float w  [GS][GS + 1];
        __shared__ float mu [GS];
        __shared__ float red[152];
        __shared__ float rdia[GS];
        const float n = (float)NTOT;

        // load + re-zero g_sig (replay invariant), 128 threads
        for (int e = tid; e < 152; e += 128) {
            red[e] = __ldcg(&g_sig[g][e]);
            g_sig[g][e] = 0.f;
        }
        __syncthreads();
        if (tid < GS) mu[tid] = red[136 + tid] / n;
        __syncthreads();

        // sigma, 128 threads x 2 elements
        for (int idx = tid; idx < 256; idx += 128) {
            const int i = idx >> 4, j = idx & 15;
            const int ii = i > j ? i : j;
            const int jj = i > j ? j : i;
            float G = red[ii * (ii + 1) / 2 + jj];
            float sh = (G - n * mu[i] * mu[j]) / (n - 1.0f);
            a[i][j] = (1.0f - 1e-6f) * sh + ((i == j) ? 1e-6f : 0.0f);
        }
        __syncthreads();

        if (tid < 32) {
            const int lane = tid;
            // Cholesky: rsqrt-based, no divides
            for (int j = 0; j < GS; j++) {
                const float d = a[j][j];
                const float r = rsqrtf(d);
                if (lane == j) a[j][j] = d * r;          // sqrt(d)
                if (lane > j && lane < GS) a[lane][j] *= r;
                __syncwarp();
                if (lane > j && lane < GS) {
                    const float lij = a[lane][j];
                    for (int k = j + 1; k <= lane; k++)
                        a[lane][k] -= lij * a[k][j];
                }
                __syncwarp();
            }

            // reciprocals of diagonal (fast divide, parallel, once)
            if (lane < GS) rdia[lane] = __fdividef(1.0f, a[lane][lane]);
            __syncwarp();

            // W = T^{-1}: lane j owns column j; divides are now multiplies
            if (lane < GS) {
                const int j = lane;
                w[j][j] = rdia[j];
                for (int i = j + 1; i < GS; i++) {
                    float s = 0.f;
                    for (int k = j; k < i; k++) s += a[i][k] * w[k][j];
                    w[i][j] = -s * rdia[i];
                }
                for (int i = j; i < GS; i++)
                    g_W[g][i * (i + 1) / 2 + j] = w[i][j];
            }
            __syncwarp();

            if (lane < GS) {
                const int i = lane;
                float b = 0.f;
                for (int j = 0; j <= i; j++) b += w[i][j] * mu[j];
                g_b[g][i] = b;
            }
            __syncwarp();
            if (tid == 0) {
                __threadfence();
                atomicExch(&g_done[g], 1);
            }
        }
    }

    if (tid == 0) {
        while (atomicAdd(&g_done[g], 0) == 0) __nanosleep(64);
    }
    __syncthreads();
    __threadfence();   // acquire g_W/g_b

    for (int i = tid; i < NPAIR + GS; i += 128) {
        if (i < NPAIR) sW[i] = g_W[g][i];
        else           sb[i - NPAIR] = g_b[g][i - NPAIR];
    }
    __syncthreads();

    const size_t base = ((size_t)m * NF + (size_t)g * GS) * HWS;

    for (int f = tid; f < NF4; f += 128) {
        float4 v[GS];
#pragma unroll
        for (int c = 0; c < GS; c++)
            v[c] = ((const float4*)(x + base + (size_t)c * HWS))[f];

        float4 y[GS];
#pragma unroll
        for (int i = 0; i < GS; i++) {
            const float b = sb[i];
            y[i].x = -b; y[i].y = -b; y[i].z = -b; y[i].w = -b;
#pragma unroll
            for (int j = 0; j <= i; j++) {
                const float w = sW[i * (i + 1) / 2 + j];
                y[i].x = fmaf(w, v[j].x, y[i].x);
                y[i].y = fmaf(w, v[j].y, y[i].y);
                y[i].z = fmaf(w, v[j].z, y[i].z);
                y[i].w = fmaf(w, v[j].w, y[i].w);
            }
        }

#pragma unroll
        for (int c = 0; c < GS; c++)
            ((float4*)(out + base + (size_t)c * HWS))[f] = y[c];
    }
}

// ---------------------------------------------------------------------------
extern "C" void kernel_launch(void* const* d_in, const int* in_sizes, int n_in,
                              void* d_out, int out_size) {
    const float* x = (const float*)d_in[0];
    float* out = (float*)d_out;

    dim3 sgrid(NG, MB, SS);
    stats_kernel<<<sgrid, 320>>>(x);
    dim3 wgrid(NG, MB);
    whiten_kernel<<<wgrid, 128>>>(x, out);
}